// round 13
// baseline (speedup 1.0000x reference)
#include <cuda_runtime.h>
#include <cuda_bf16.h>
#include <math.h>

// Problem constants (fixed by reference: x,y (4,2,32768) fp32, max_shift=128)
constexpr int T  = 32768;
constexpr int P  = 8;      // B*C pairs
constexpr int MS = 128;    // max_shift
constexpr int S  = 2 * MS + 1;  // 257 shifts

// Tiling: 512 blocks (64 chunks x 8 pairs) of 256 threads (8 warps).
// Warp tz = time slice; lane g = shifts [8g, 8g+8) (0..255).
// Shift 256 piggy-backs on the stats pass.
constexpr int CHK    = 512;
constexpr int NCHUNK = T / CHK;   // 64
constexpr int Z      = 8;         // warps per block
constexpr int G      = 32;        // shift groups of 8
constexpr int BD     = Z * G;     // 256 threads
constexpr int STEPS  = CHK / Z;   // 64 timesteps per thread
constexpr int ITERS  = STEPS / 4; // 16 (fully unrolled)
constexpr int XH     = 784;       // x tile + halo floats
constexpr int XQ     = XH / 4;    // 196 quads
constexpr int XEQ    = XQ / 2;    // 98 quads per parity array

// Global accumulators (zero-initialized; finalize re-zeroes them each launch)
__device__ float g_part[P][S];     // [pair][shift] — accumulated via atomicAdd
__device__ float g_stats[P][4];    // [pair][{Sy,Syy,Sx,Sxx}] — atomicAdd
__device__ int   g_cnt[P];         // completion counters

__global__ __launch_bounds__(BD, 4) void corr_fused(const float* __restrict__ x,
                                                    const float* __restrict__ y,
                                                    float* __restrict__ out) {
    // x tile de-interleaved by float4 parity -> conflict-free LDS in mainloop
    __shared__ __align__(16) float xEf[XEQ * 4];
    __shared__ __align__(16) float xOf[XEQ * 4];
    __shared__ __align__(16) float smy[CHK];
    __shared__ float red[Z][G][8];
    __shared__ float wstats[8][5];         // {Sy,Syy,Sx,Sxx,s256} per warp
    __shared__ int   isLast;
    __shared__ float2 scH[MS], scT[MS];    // boundary prefix sums (x, x^2)
    __shared__ float tot[4];

    const int chunk = blockIdx.x;
    const int pair  = blockIdx.y;
    const float* xp = x + pair * T;
    const float* yp = y + pair * T;
    const int cbase = chunk * CHK;
    const int tid   = threadIdx.x;

    float4* xE4 = reinterpret_cast<float4*>(xEf);
    float4* xO4 = reinterpret_cast<float4*>(xOf);

    // ---- load tiles (logical tile idx i = x_pad[cbase - MS + i]) ----
    if (chunk >= 1 && chunk <= NCHUNK - 2) {
        if (tid < XQ) {
            const float4 v = reinterpret_cast<const float4*>(xp + cbase - MS)[tid];
            if (tid & 1) xO4[tid >> 1] = v;
            else         xE4[tid >> 1] = v;
        }
    } else {
        for (int i = tid; i < XH; i += BD) {
            int gi = cbase - MS + i;
            float v = (gi >= 0 && gi < T) ? xp[gi] : 0.0f;
            int q = i >> 2, e = i & 3;
            if (q & 1) xOf[(q >> 1) * 4 + e] = v;
            else       xEf[(q >> 1) * 4 + e] = v;
        }
    }
    {
        const float4* yg = reinterpret_cast<const float4*>(yp + cbase);
        if (tid < CHK / 4) reinterpret_cast<float4*>(smy)[tid] = yg[tid];
    }
    __syncthreads();

    // ---- shifted dot products: 8 shifts/thread, warp-aligned, fmaf chains ----
    const int g  = tid & 31;         // lane = shift group
    const int tz = tid >> 5;         // warp = time slice
    const int yi = tz * (STEPS / 4); // first y quad (even)
    const int base = (yi >> 1) + g;  // parity index of x quad yi + 2g

    const float4* y4 = reinterpret_cast<const float4*>(smy);

    float a0 = 0.f, a1 = 0.f, a2 = 0.f, a3 = 0.f;
    float a4 = 0.f, a5 = 0.f, a6 = 0.f, a7 = 0.f;

    float4 w0 = xE4[base];
    float4 w1 = xO4[base];

    #pragma unroll
    for (int it = 0; it < ITERS; ++it) {
        const float4 w2 = (it & 1) ? xO4[base + ((it + 1) >> 1)]
                                   : xE4[base + 1 + (it >> 1)];
        const float4 yv = y4[yi + it];   // per-warp broadcast

        a0 = fmaf(yv.x, w0.x, a0); a0 = fmaf(yv.y, w0.y, a0);
        a0 = fmaf(yv.z, w0.z, a0); a0 = fmaf(yv.w, w0.w, a0);
        a1 = fmaf(yv.x, w0.y, a1); a1 = fmaf(yv.y, w0.z, a1);
        a1 = fmaf(yv.z, w0.w, a1); a1 = fmaf(yv.w, w1.x, a1);
        a2 = fmaf(yv.x, w0.z, a2); a2 = fmaf(yv.y, w0.w, a2);
        a2 = fmaf(yv.z, w1.x, a2); a2 = fmaf(yv.w, w1.y, a2);
        a3 = fmaf(yv.x, w0.w, a3); a3 = fmaf(yv.y, w1.x, a3);
        a3 = fmaf(yv.z, w1.y, a3); a3 = fmaf(yv.w, w1.z, a3);
        a4 = fmaf(yv.x, w1.x, a4); a4 = fmaf(yv.y, w1.y, a4);
        a4 = fmaf(yv.z, w1.z, a4); a4 = fmaf(yv.w, w1.w, a4);
        a5 = fmaf(yv.x, w1.y, a5); a5 = fmaf(yv.y, w1.z, a5);
        a5 = fmaf(yv.z, w1.w, a5); a5 = fmaf(yv.w, w2.x, a5);
        a6 = fmaf(yv.x, w1.z, a6); a6 = fmaf(yv.y, w1.w, a6);
        a6 = fmaf(yv.z, w2.x, a6); a6 = fmaf(yv.w, w2.y, a6);
        a7 = fmaf(yv.x, w1.w, a7); a7 = fmaf(yv.y, w2.x, a7);
        a7 = fmaf(yv.z, w2.y, a7); a7 = fmaf(yv.w, w2.z, a7);

        w0 = w1;
        w1 = w2;
    }

    red[tz][g][0] = a0; red[tz][g][1] = a1;
    red[tz][g][2] = a2; red[tz][g][3] = a3;
    red[tz][g][4] = a4; red[tz][g][5] = a5;
    red[tz][g][6] = a6; red[tz][g][7] = a7;

    // ---- per-chunk statistics + shift-256 (after mainloop: registers reused) ----
    {
        float ly = 0.f, lyy = 0.f, lx = 0.f, lxx = 0.f, s256 = 0.f;
        #pragma unroll
        for (int r = 0; r < CHK / 256; r++) {
            const int i = tid + 256 * r;
            const float yv = smy[i];
            ly += yv; lyy = fmaf(yv, yv, lyy);
            {   // x_pad tile idx MS + i
                int q = (MS + i) >> 2, e = i & 3;
                float xv = (q & 1) ? xOf[(q >> 1) * 4 + e] : xEf[(q >> 1) * 4 + e];
                lx += xv; lxx = fmaf(xv, xv, lxx);
            }
            {   // shift 256: x_pad tile idx 2*MS + i
                int q = (2 * MS + i) >> 2, e = i & 3;
                float xv = (q & 1) ? xOf[(q >> 1) * 4 + e] : xEf[(q >> 1) * 4 + e];
                s256 = fmaf(xv, yv, s256);
            }
        }
        #pragma unroll
        for (int o = 16; o; o >>= 1) {
            ly   += __shfl_down_sync(0xffffffffu, ly,   o);
            lyy  += __shfl_down_sync(0xffffffffu, lyy,  o);
            lx   += __shfl_down_sync(0xffffffffu, lx,   o);
            lxx  += __shfl_down_sync(0xffffffffu, lxx,  o);
            s256 += __shfl_down_sync(0xffffffffu, s256, o);
        }
        if ((tid & 31) == 0) {
            int w = tid >> 5;
            wstats[w][0] = ly; wstats[w][1] = lyy;
            wstats[w][2] = lx; wstats[w][3] = lxx;
            wstats[w][4] = s256;
        }
    }
    __syncthreads();

    // ---- accumulate into L2 via fire-and-forget float atomics (REDG) ----
    {
        const int gg = tid >> 3;
        const int j  = tid & 7;
        float s = 0.f;
        #pragma unroll
        for (int z = 0; z < Z; z++) s += red[z][gg][j];
        atomicAdd(&g_part[pair][tid], s);
    }
    if (tid < 5) {
        float s = 0.f;
        #pragma unroll
        for (int w = 0; w < 8; w++) s += wstats[w][tid];
        if (tid < 4) atomicAdd(&g_stats[pair][tid], s);
        else         atomicAdd(&g_part[pair][256],  s);
    }
    __syncthreads();

    // ---- completion handshake: last block of this pair finalizes ----
    if (tid == 0) {
        __threadfence();
        int old = atomicAdd(&g_cnt[pair], 1);
        isLast = (old == NCHUNK - 1) ? 1 : 0;
    }
    __syncthreads();
    if (!isLast) return;
    __threadfence();

    // =================== FINALIZE (one block per pair, tiny now) ===================
    if (tid < MS) {
        float v = xp[tid];
        scH[tid] = make_float2(v, v * v);
    } else {
        int j = tid - MS;
        float v = xp[T - 1 - j];
        scT[j] = make_float2(v, v * v);
    }
    if (tid < 4) tot[tid] = __ldcg(&g_stats[pair][tid]);   // L1-bypass: see atomics
    __syncthreads();

    // Hillis-Steele inclusive scans over head and reversed tail (128 each)
    #pragma unroll
    for (int o = 1; o < MS; o <<= 1) {
        float2* arr = (tid < MS) ? scH : scT;
        const int j = (tid < MS) ? tid : tid - MS;
        float2 v = arr[j];
        if (j >= o) { v.x += arr[j - o].x; v.y += arr[j - o].y; }
        __syncthreads();
        arr[j] = v;
        __syncthreads();
    }

    // ---- per-shift final Pearson value (257 shifts, 2 rounds) ----
    const float Sy  = tot[0], Syy = tot[1];
    const float Sx  = tot[2], Sxx = tot[3];
    const float invT = 1.0f / (float)T;
    const float my   = Sy * invT;
    const float vyy  = Syy - my * Sy;         // sum((y - my)^2)

    for (int s = tid; s < S; s += BD) {
        const float part = __ldcg(&g_part[pair][s]);

        const int d = s - MS;
        float bx = 0.f, bxx = 0.f;
        if (d > 0)      { float2 h = scH[d - 1];   bx = h.x;  bxx = h.y; }
        else if (d < 0) { float2 t2 = scT[-d - 1]; bx = t2.x; bxx = t2.y; }

        const float wsx  = Sx  - bx;
        const float wsxx = Sxx - bxx;
        const float num  = part - my * wsx;           // sum(xw * yc)
        const float vxx  = wsxx - wsx * wsx * invT;   // sum((xw - mean_xw)^2)
        out[s * P + pair] = num * rsqrtf(vxx * vyy);

        g_part[pair][s] = 0.0f;   // reset accumulator for next graph replay
    }
    if (tid < 4) g_stats[pair][tid] = 0.0f;

    __syncthreads();
    if (tid == 0) { __threadfence(); g_cnt[pair] = 0; }
}

extern "C" void kernel_launch(void* const* d_in, const int* in_sizes, int n_in,
                              void* d_out, int out_size) {
    const float* x = (const float*)d_in[0];
    const float* y = (const float*)d_in[1];
    float* out = (float*)d_out;

    corr_fused<<<dim3(NCHUNK, P), BD>>>(x, y, out);
}

// round 14
// speedup vs baseline: 1.0226x; 1.0226x over previous
#include <cuda_runtime.h>
#include <cuda_bf16.h>
#include <math.h>

// Problem constants (fixed by reference: x,y (4,2,32768) fp32, max_shift=128)
constexpr int T  = 32768;
constexpr int P  = 8;      // B*C pairs
constexpr int MS = 128;    // max_shift
constexpr int S  = 2 * MS + 1;  // 257 shifts

// Tiling: 512 blocks (64 chunks x 8 pairs) of 256 threads (8 warps).
// Warp tz = time slice; lane g = shifts [8g, 8g+8) (0..255).
// Shift 256 piggy-backs on the stats pass.
constexpr int CHK    = 512;
constexpr int NCHUNK = T / CHK;   // 64
constexpr int Z      = 8;         // warps per block
constexpr int G      = 32;        // shift groups of 8
constexpr int BD     = Z * G;     // 256 threads
constexpr int STEPS  = CHK / Z;   // 64 timesteps per thread
constexpr int ITERS  = STEPS / 4; // 16 (fully unrolled)
constexpr int XH     = 784;       // x tile + halo floats
constexpr int XQ     = XH / 4;    // 196 quads
constexpr int XEQ    = XQ / 2;    // 98 quads per parity array
constexpr int YPAD   = 16;        // y tile pad (one quad per warp prefetch overrun)

// Global accumulators (zero-initialized; finalize re-zeroes them each launch)
__device__ float g_part[P][S];     // [pair][shift] — accumulated via atomicAdd
__device__ float g_stats[P][4];    // [pair][{Sy,Syy,Sx,Sxx}] — atomicAdd
__device__ int   g_cnt[P];         // completion counters

__global__ __launch_bounds__(BD, 4) void corr_fused(const float* __restrict__ x,
                                                    const float* __restrict__ y,
                                                    float* __restrict__ out) {
    // x tile de-interleaved by float4 parity -> conflict-free LDS in mainloop
    __shared__ __align__(16) float xEf[XEQ * 4];
    __shared__ __align__(16) float xOf[XEQ * 4];
    __shared__ __align__(16) float smy[CHK + YPAD];
    __shared__ float red[Z][G][8];
    __shared__ float wstats[8][5];         // {Sy,Syy,Sx,Sxx,s256} per warp
    __shared__ int   isLast;
    __shared__ float2 scH[MS], scT[MS];    // boundary prefix sums (x, x^2)
    __shared__ float tot[4];

    const int chunk = blockIdx.x;
    const int pair  = blockIdx.y;
    const float* xp = x + pair * T;
    const float* yp = y + pair * T;
    const int cbase = chunk * CHK;
    const int tid   = threadIdx.x;

    float4* xE4 = reinterpret_cast<float4*>(xEf);
    float4* xO4 = reinterpret_cast<float4*>(xOf);

    // ---- load tiles (logical tile idx i = x_pad[cbase - MS + i]) ----
    if (chunk >= 1 && chunk <= NCHUNK - 2) {
        if (tid < XQ) {
            const float4 v = reinterpret_cast<const float4*>(xp + cbase - MS)[tid];
            if (tid & 1) xO4[tid >> 1] = v;
            else         xE4[tid >> 1] = v;
        }
    } else {
        for (int i = tid; i < XH; i += BD) {
            int gi = cbase - MS + i;
            float v = (gi >= 0 && gi < T) ? xp[gi] : 0.0f;
            int q = i >> 2, e = i & 3;
            if (q & 1) xOf[(q >> 1) * 4 + e] = v;
            else       xEf[(q >> 1) * 4 + e] = v;
        }
    }
    {
        const float4* yg = reinterpret_cast<const float4*>(yp + cbase);
        if (tid < CHK / 4) reinterpret_cast<float4*>(smy)[tid] = yg[tid];
        else if (tid < CHK / 4 + YPAD / 4)
            reinterpret_cast<float4*>(smy)[tid] = make_float4(0.f, 0.f, 0.f, 0.f);
    }
    __syncthreads();

    // ---- shifted dot products: 8 shifts/thread, warp-aligned, y software-pipelined ----
    const int g  = tid & 31;         // lane = shift group
    const int tz = tid >> 5;         // warp = time slice
    const int yi = tz * (STEPS / 4); // first y quad (even)
    const int base = (yi >> 1) + g;  // parity index of x quad yi + 2g

    const float4* y4 = reinterpret_cast<const float4*>(smy);

    float a0 = 0.f, a1 = 0.f, a2 = 0.f, a3 = 0.f;
    float a4 = 0.f, a5 = 0.f, a6 = 0.f, a7 = 0.f;

    float4 w0 = xE4[base];
    float4 w1 = xO4[base];
    float4 yv = y4[yi];              // pipelined: current y quad

    #pragma unroll
    for (int it = 0; it < ITERS; ++it) {
        const float4 w2 = (it & 1) ? xO4[base + ((it + 1) >> 1)]
                                   : xE4[base + 1 + (it >> 1)];
        const float4 yn = y4[yi + it + 1];   // prefetch next (pad keeps it in-bounds)

        a0 = fmaf(yv.x, w0.x, a0); a0 = fmaf(yv.y, w0.y, a0);
        a0 = fmaf(yv.z, w0.z, a0); a0 = fmaf(yv.w, w0.w, a0);
        a1 = fmaf(yv.x, w0.y, a1); a1 = fmaf(yv.y, w0.z, a1);
        a1 = fmaf(yv.z, w0.w, a1); a1 = fmaf(yv.w, w1.x, a1);
        a2 = fmaf(yv.x, w0.z, a2); a2 = fmaf(yv.y, w0.w, a2);
        a2 = fmaf(yv.z, w1.x, a2); a2 = fmaf(yv.w, w1.y, a2);
        a3 = fmaf(yv.x, w0.w, a3); a3 = fmaf(yv.y, w1.x, a3);
        a3 = fmaf(yv.z, w1.y, a3); a3 = fmaf(yv.w, w1.z, a3);
        a4 = fmaf(yv.x, w1.x, a4); a4 = fmaf(yv.y, w1.y, a4);
        a4 = fmaf(yv.z, w1.z, a4); a4 = fmaf(yv.w, w1.w, a4);
        a5 = fmaf(yv.x, w1.y, a5); a5 = fmaf(yv.y, w1.z, a5);
        a5 = fmaf(yv.z, w1.w, a5); a5 = fmaf(yv.w, w2.x, a5);
        a6 = fmaf(yv.x, w1.z, a6); a6 = fmaf(yv.y, w1.w, a6);
        a6 = fmaf(yv.z, w2.x, a6); a6 = fmaf(yv.w, w2.y, a6);
        a7 = fmaf(yv.x, w1.w, a7); a7 = fmaf(yv.y, w2.x, a7);
        a7 = fmaf(yv.z, w2.y, a7); a7 = fmaf(yv.w, w2.z, a7);

        yv = yn;   // pure renaming under full unroll
        w0 = w1;
        w1 = w2;
    }

    red[tz][g][0] = a0; red[tz][g][1] = a1;
    red[tz][g][2] = a2; red[tz][g][3] = a3;
    red[tz][g][4] = a4; red[tz][g][5] = a5;
    red[tz][g][6] = a6; red[tz][g][7] = a7;

    // ---- per-chunk statistics + shift-256 (after mainloop: registers reused) ----
    {
        float ly = 0.f, lyy = 0.f, lx = 0.f, lxx = 0.f, s256 = 0.f;
        #pragma unroll
        for (int r = 0; r < CHK / 256; r++) {
            const int i = tid + 256 * r;
            const float yval = smy[i];
            ly += yval; lyy = fmaf(yval, yval, lyy);
            {   // x_pad tile idx MS + i
                int q = (MS + i) >> 2, e = i & 3;
                float xv = (q & 1) ? xOf[(q >> 1) * 4 + e] : xEf[(q >> 1) * 4 + e];
                lx += xv; lxx = fmaf(xv, xv, lxx);
            }
            {   // shift 256: x_pad tile idx 2*MS + i
                int q = (2 * MS + i) >> 2, e = i & 3;
                float xv = (q & 1) ? xOf[(q >> 1) * 4 + e] : xEf[(q >> 1) * 4 + e];
                s256 = fmaf(xv, yval, s256);
            }
        }
        #pragma unroll
        for (int o = 16; o; o >>= 1) {
            ly   += __shfl_down_sync(0xffffffffu, ly,   o);
            lyy  += __shfl_down_sync(0xffffffffu, lyy,  o);
            lx   += __shfl_down_sync(0xffffffffu, lx,   o);
            lxx  += __shfl_down_sync(0xffffffffu, lxx,  o);
            s256 += __shfl_down_sync(0xffffffffu, s256, o);
        }
        if ((tid & 31) == 0) {
            int w = tid >> 5;
            wstats[w][0] = ly; wstats[w][1] = lyy;
            wstats[w][2] = lx; wstats[w][3] = lxx;
            wstats[w][4] = s256;
        }
    }
    __syncthreads();

    // ---- accumulate into L2 via fire-and-forget float atomics (REDG) ----
    {
        const int gg = tid >> 3;
        const int j  = tid & 7;
        float s = 0.f;
        #pragma unroll
        for (int z = 0; z < Z; z++) s += red[z][gg][j];
        atomicAdd(&g_part[pair][tid], s);
    }
    if (tid < 5) {
        float s = 0.f;
        #pragma unroll
        for (int w = 0; w < 8; w++) s += wstats[w][tid];
        if (tid < 4) atomicAdd(&g_stats[pair][tid], s);
        else         atomicAdd(&g_part[pair][256],  s);
    }
    __syncthreads();

    // ---- completion handshake: last block of this pair finalizes ----
    if (tid == 0) {
        __threadfence();
        int old = atomicAdd(&g_cnt[pair], 1);
        isLast = (old == NCHUNK - 1) ? 1 : 0;
    }
    __syncthreads();
    if (!isLast) return;
    __threadfence();

    // =================== FINALIZE (one block per pair, tiny) ===================
    if (tid < MS) {
        float v = xp[tid];
        scH[tid] = make_float2(v, v * v);
    } else {
        int j = tid - MS;
        float v = xp[T - 1 - j];
        scT[j] = make_float2(v, v * v);
    }
    if (tid < 4) tot[tid] = __ldcg(&g_stats[pair][tid]);
    __syncthreads();

    // Hillis-Steele inclusive scans over head and reversed tail (128 each)
    #pragma unroll
    for (int o = 1; o < MS; o <<= 1) {
        float2* arr = (tid < MS) ? scH : scT;
        const int j = (tid < MS) ? tid : tid - MS;
        float2 v = arr[j];
        if (j >= o) { v.x += arr[j - o].x; v.y += arr[j - o].y; }
        __syncthreads();
        arr[j] = v;
        __syncthreads();
    }

    // ---- per-shift final Pearson value (257 shifts, 2 rounds) ----
    const float Sy  = tot[0], Syy = tot[1];
    const float Sx  = tot[2], Sxx = tot[3];
    const float invT = 1.0f / (float)T;
    const float my   = Sy * invT;
    const float vyy  = Syy - my * Sy;         // sum((y - my)^2)

    for (int s = tid; s < S; s += BD) {
        const float part = __ldcg(&g_part[pair][s]);

        const int d = s - MS;
        float bx = 0.f, bxx = 0.f;
        if (d > 0)      { float2 h = scH[d - 1];   bx = h.x;  bxx = h.y; }
        else if (d < 0) { float2 t2 = scT[-d - 1]; bx = t2.x; bxx = t2.y; }

        const float wsx  = Sx  - bx;
        const float wsxx = Sxx - bxx;
        const float num  = part - my * wsx;           // sum(xw * yc)
        const float vxx  = wsxx - wsx * wsx * invT;   // sum((xw - mean_xw)^2)
        out[s * P + pair] = num * rsqrtf(vxx * vyy);

        g_part[pair][s] = 0.0f;   // reset accumulator for next graph replay
    }
    if (tid < 4) g_stats[pair][tid] = 0.0f;

    __syncthreads();
    if (tid == 0) { __threadfence(); g_cnt[pair] = 0; }
}

extern "C" void kernel_launch(void* const* d_in, const int* in_sizes, int n_in,
                              void* d_out, int out_size) {
    const float* x = (const float*)d_in[0];
    const float* y = (const float*)d_in[1];
    float* out = (float*)d_out;

    corr_fused<<<dim3(NCHUNK, P), BD>>>(x, y, out);
}